// round 14
// baseline (speedup 1.0000x reference)
#include <cuda_runtime.h>

#define BATCH 64
#define NJ 21
#define BJ (BATCH * NJ)        // 1344
#define IMG 256
#define N_MEMSET 800           // maps [0, 800) zero-filled by CE + patched
#define N_DENSE  (BJ - N_MEMSET) // maps [800, 1344) written densely by SMs
#define PPX 121                // 11x11 patch pixels

__device__ int2 g_seeds[N_MEMSET];

// w[d] = exp(-d^2 / (2 * 2.5^2)) = exp(-d^2 / 12.5), d = 0..5
__constant__ float c_w[6] = {
    1.0f,
    0.92311634638663580f,   // exp(-0.08)
    0.72614903707369090f,   // exp(-0.32)
    0.48675225595997170f,   // exp(-0.72)
    0.27803730045319410f,   // exp(-1.28)
    0.13533528323661270f    // exp(-2.00)
};

// Fisheye seed in double: matches jnp round-half-to-even exactly; avoids trig
// via cos(phi)=x/rho, sin(phi)=y/rho.
__device__ __forceinline__ int2 project(const float* __restrict__ joint, unsigned bj) {
    double x = (double)joint[bj * 3 + 0];
    double y = (double)joint[bj * 3 + 1];
    double z = (double)joint[bj * 3 + 2];
    double rho = sqrt(x * x + y * y);
    double theta = atan2(rho, z);
    double r = 128.0 * theta / 1.5707963267948966;  // RADIUS * theta / (pi/2)
    double cphi, sphi;
    if (rho > 0.0) { cphi = x / rho; sphi = y / rho; }
    else           { cphi = 1.0;     sphi = 0.0;     }
    int sx = (int)rint(128.0 + r * cphi);
    int sy = (int)rint(128.0 + r * sphi);
    sx = min(max(sx, 0), IMG - 1);
    sy = min(max(sy, 0), IMG - 1);
    return make_int2(sx, sy);
}

// Seeds for the memset-route maps, one thread each, spread across SMs.
__global__ void __launch_bounds__(32) seed_kernel(const float* __restrict__ joint) {
    int i = blockIdx.x * 32 + threadIdx.x;
    if (i < N_MEMSET) g_seeds[i] = project(joint, i);
}

// Dense writer for maps [N_MEMSET, BJ): one block per map, 512 threads,
// 32-deep float4 store streams (the proven 6.3 TB/s configuration).
__global__ void __launch_bounds__(512) hm_kernel(float4* __restrict__ out,
                                                 const float* __restrict__ joint) {
    __shared__ int2 s_seed;
    const unsigned bj = N_MEMSET + blockIdx.x;

    if (threadIdx.x == 0) s_seed = project(joint, bj);
    __syncthreads();
    const int2 s = s_seed;

    const unsigned tid = threadIdx.x;
    const unsigned x0  = (tid & 63u) << 2;

    float4 wx;
    {
        float* wxp = reinterpret_cast<float*>(&wx);
#pragma unroll
        for (int k = 0; k < 4; k++) {
            int dx  = (int)(x0 + k) - s.x;
            int adx = dx < 0 ? -dx : dx;
            wxp[k] = (adx <= 5) ? c_w[adx] : 0.0f;
        }
    }

    const int    y_first = (int)(tid >> 6);
    float4* o = out + (size_t)bj * (IMG * IMG / 4) + tid;

#pragma unroll
    for (int k = 0; k < 32; k++) {
        int y   = y_first + k * 8;
        int dy  = y - s.y;
        int ady = dy < 0 ? -dy : dy;
        float wy = (ady <= 5) ? c_w[ady] : 0.0f;
        __stcg(o + (size_t)k * 512,
               make_float4(wy * wx.x, wy * wx.y, wy * wx.z, wy * wx.w));
    }
}

// Stamp 11x11 gaussian patches onto the zeroed maps [0, N_MEMSET).
// One thread per (map, patch-pixel); seed loads L2-broadcast.
__global__ void __launch_bounds__(256) patch_kernel(float* __restrict__ out) {
    const unsigned i = blockIdx.x * 256u + threadIdx.x;
    if (i >= N_MEMSET * PPX) return;

    const unsigned bj = i / PPX;
    const unsigned t  = i - bj * PPX;

    const int2 s = g_seeds[bj];
    const int dy = (int)(t / 11) - 5;
    const int dx = (int)(t % 11) - 5;
    const int y  = s.y + dy;
    const int x  = s.x + dx;
    if ((unsigned)y < IMG && (unsigned)x < IMG) {
        const int ady = dy < 0 ? -dy : dy;
        const int adx = dx < 0 ? -dx : dx;
        out[(size_t)bj * (IMG * IMG) + (size_t)y * IMG + x] = c_w[ady] * c_w[adx];
    }
}

extern "C" void kernel_launch(void* const* d_in, const int* in_sizes, int n_in,
                              void* d_out, int out_size) {
    const float* joint = (const float*)d_in[0];
    float* out = (float*)d_out;

    // Created once (first, uncaptured correctness call); reused every call so
    // the captured graph is identical on each capture. No device allocations.
    static cudaStream_t s2 = nullptr;
    static cudaEvent_t evFork = nullptr, evJoin = nullptr;
    if (!s2) {
        cudaStreamCreateWithFlags(&s2, cudaStreamNonBlocking);
        cudaEventCreateWithFlags(&evFork, cudaEventDisableTiming);
        cudaEventCreateWithFlags(&evJoin, cudaEventDisableTiming);
    }

    // Fork: CE zero-fill of maps [0, N_MEMSET) runs concurrently with the
    // SM dense writer for maps [N_MEMSET, BJ).
    cudaEventRecord(evFork, 0);
    cudaStreamWaitEvent(s2, evFork, 0);
    cudaMemsetAsync(out, 0, (size_t)N_MEMSET * IMG * IMG * sizeof(float), s2);

    // Main stream: seeds for the patched maps, then the dense half.
    seed_kernel<<<(N_MEMSET + 31) / 32, 32>>>(joint);
    hm_kernel<<<N_DENSE, 512>>>((float4*)out, joint);

    // Join: patches must land after the memset (and after dense, by stream order).
    cudaEventRecord(evJoin, s2);
    cudaStreamWaitEvent(0, evJoin, 0);
    patch_kernel<<<(N_MEMSET * PPX + 255) / 256, 256>>>(out);
}

// round 15
// speedup vs baseline: 1.4193x; 1.4193x over previous
#include <cuda_runtime.h>

#define BATCH 64
#define NJ 21
#define BJ (BATCH * NJ)        // 1344
#define IMG 256

// w[d] = exp(-d^2 / (2 * 2.5^2)) = exp(-d^2 / 12.5), d = 0..5
__constant__ float c_w[6] = {
    1.0f,
    0.92311634638663580f,   // exp(-0.08)
    0.72614903707369090f,   // exp(-0.32)
    0.48675225595997170f,   // exp(-0.72)
    0.27803730045319410f,   // exp(-1.28)
    0.13533528323661270f    // exp(-2.00)
};

// One block = one full (batch, joint) 256x256 map.
// 512 threads, each thread writes 32 float4 (lane-contiguous per store,
// 8 KB contiguous per unrolled step). Stores use __stcg (L2 write-back,
// L1 bypass) — pure write stream never re-reads, L1 adds no value.
// Thread 0 computes the fisheye seed for this map in double (matches jnp
// round-half-to-even exactly; avoids trig via cos(phi)=x/rho, sin(phi)=y/rho).
__global__ void __launch_bounds__(512) hm_kernel(float4* __restrict__ out,
                                                 const float* __restrict__ joint) {
    __shared__ int2 s_seed;

    const unsigned bj = blockIdx.x;

    if (threadIdx.x == 0) {
        double x = (double)joint[bj * 3 + 0];
        double y = (double)joint[bj * 3 + 1];
        double z = (double)joint[bj * 3 + 2];
        double rho = sqrt(x * x + y * y);
        double theta = atan2(rho, z);
        double r = 128.0 * theta / 1.5707963267948966;  // RADIUS * theta / (pi/2)
        double cphi, sphi;
        if (rho > 0.0) { cphi = x / rho; sphi = y / rho; }
        else           { cphi = 1.0;     sphi = 0.0;     }
        int sx = (int)rint(128.0 + r * cphi);
        int sy = (int)rint(128.0 + r * sphi);
        sx = min(max(sx, 0), IMG - 1);
        sy = min(max(sy, 0), IMG - 1);
        s_seed = make_int2(sx, sy);
    }
    __syncthreads();
    const int2 s = s_seed;

    const unsigned tid = threadIdx.x;
    const unsigned x0  = (tid & 63u) << 2;      // column of this thread's float4

    // Column weights: invariant across all 32 rows this thread touches.
    float4 wx;
    {
        float* wxp = reinterpret_cast<float*>(&wx);
#pragma unroll
        for (int k = 0; k < 4; k++) {
            int dx  = (int)(x0 + k) - s.x;
            int adx = dx < 0 ? -dx : dx;
            wxp[k] = (adx <= 5) ? c_w[adx] : 0.0f;
        }
    }

    const int    y_first = (int)(tid >> 6);     // row at k=0; +8 per k
    const size_t base    = (size_t)bj * (IMG * IMG / 4) + tid;
    float4* o = out + base;

#pragma unroll
    for (int k = 0; k < 32; k++) {
        int y   = y_first + k * 8;
        int dy  = y - s.y;
        int ady = dy < 0 ? -dy : dy;
        float wy = (ady <= 5) ? c_w[ady] : 0.0f;
        __stcg(o + (size_t)k * 512,
               make_float4(wy * wx.x, wy * wx.y, wy * wx.z, wy * wx.w));
    }
}

extern "C" void kernel_launch(void* const* d_in, const int* in_sizes, int n_in,
                              void* d_out, int out_size) {
    const float* joint = (const float*)d_in[0];
    // 1344 maps, one block each, 512 threads
    hm_kernel<<<BJ, 512>>>((float4*)d_out, joint);
}

// round 16
// speedup vs baseline: 1.4359x; 1.0117x over previous
#include <cuda_runtime.h>

#define BATCH 64
#define NJ 21
#define BJ (BATCH * NJ)        // 1344
#define IMG 256

// w[d] = exp(-d^2 / (2 * 2.5^2)) = exp(-d^2 / 12.5), d = 0..5
__constant__ float c_w[6] = {
    1.0f,
    0.92311634638663580f,   // exp(-0.08)
    0.72614903707369090f,   // exp(-0.32)
    0.48675225595997170f,   // exp(-0.72)
    0.27803730045319410f,   // exp(-1.28)
    0.13533528323661270f    // exp(-2.00)
};

// One block = TWO (batch, joint) 256x256 maps (64-deep store stream/thread).
// 512 threads, each thread writes 64 float4 (lane-contiguous per store,
// 8 KB contiguous per unrolled step). __stcg: L2 write-back, L1 bypass.
// Threads 0 and 1 compute the two fisheye seeds in double (matches jnp
// round-half-to-even exactly; avoids trig via cos(phi)=x/rho, sin(phi)=y/rho).
__global__ void __launch_bounds__(512) hm_kernel(float4* __restrict__ out,
                                                 const float* __restrict__ joint) {
    __shared__ int2 s_seed[2];

    const unsigned bj0 = blockIdx.x * 2u;

    if (threadIdx.x < 2) {
        const unsigned bj = bj0 + threadIdx.x;
        double x = (double)joint[bj * 3 + 0];
        double y = (double)joint[bj * 3 + 1];
        double z = (double)joint[bj * 3 + 2];
        double rho = sqrt(x * x + y * y);
        double theta = atan2(rho, z);
        double r = 128.0 * theta / 1.5707963267948966;  // RADIUS * theta / (pi/2)
        double cphi, sphi;
        if (rho > 0.0) { cphi = x / rho; sphi = y / rho; }
        else           { cphi = 1.0;     sphi = 0.0;     }
        int sx = (int)rint(128.0 + r * cphi);
        int sy = (int)rint(128.0 + r * sphi);
        sx = min(max(sx, 0), IMG - 1);
        sy = min(max(sy, 0), IMG - 1);
        s_seed[threadIdx.x] = make_int2(sx, sy);
    }
    __syncthreads();

    const unsigned tid = threadIdx.x;
    const unsigned x0  = (tid & 63u) << 2;      // column of this thread's float4
    const int      y_first = (int)(tid >> 6);   // row at k=0; +8 per k

#pragma unroll
    for (int m = 0; m < 2; m++) {
        const int2 s = s_seed[m];

        // Column weights: invariant across all 32 rows this thread touches.
        float4 wx;
        {
            float* wxp = reinterpret_cast<float*>(&wx);
#pragma unroll
            for (int k = 0; k < 4; k++) {
                int dx  = (int)(x0 + k) - s.x;
                int adx = dx < 0 ? -dx : dx;
                wxp[k] = (adx <= 5) ? c_w[adx] : 0.0f;
            }
        }

        float4* o = out + (size_t)(bj0 + m) * (IMG * IMG / 4) + tid;

#pragma unroll
        for (int k = 0; k < 32; k++) {
            int y   = y_first + k * 8;
            int dy  = y - s.y;
            int ady = dy < 0 ? -dy : dy;
            float wy = (ady <= 5) ? c_w[ady] : 0.0f;
            __stcg(o + (size_t)k * 512,
                   make_float4(wy * wx.x, wy * wx.y, wy * wx.z, wy * wx.w));
        }
    }
}

extern "C" void kernel_launch(void* const* d_in, const int* in_sizes, int n_in,
                              void* d_out, int out_size) {
    const float* joint = (const float*)d_in[0];
    // 672 blocks, two maps each, 512 threads
    hm_kernel<<<BJ / 2, 512>>>((float4*)d_out, joint);
}